// round 15
// baseline (speedup 1.0000x reference)
#include <cuda_runtime.h>
#include <cuda_fp16.h>
#include <cstdint>

// ---------------------------------------------------------------------------
// GraphBackboneGCN: 3x (GCNConv + ReLU) + global mean pool.
// R15: R13 base (best: 161.4us) + ONE change: gather loads use __ldcg
//      (L2-only) to stop L1 thrash from random 256B row reads.
//      (R14's replica-cursor fill + 8-edge unroll reverted: net regression.)
// ---------------------------------------------------------------------------

#define NMAX 50176
#define EMAX 1048576
#define D 128
#define NGRAPH 512
#define CREP 4

#define SCAN_T 1024
#define SCAN_V 4
#define SCAN_ELEMS (SCAN_T * SCAN_V)   // 4096 = 1<<12

__device__ __align__(128) __half g_h1[(size_t)NMAX * D];   // agg out (fp16)
__device__ __align__(128) __half g_h2[(size_t)NMAX * D];   // gemm out / gather src
__device__ float g_dinv[NMAX];
__device__ int   g_cnt[NMAX];                  // fill cursor (zeroed once)
__device__ int   g_cntR[CREP][NMAX];           // replicated count histogram
__device__ int   g_off[NMAX + 1];              // block-LOCAL exclusive offsets
__device__ int   g_bsum[64];                   // per-scan1-block totals
__device__ __align__(128) int2 g_csr[EMAX];    // .x = src, .y = coef bits
__device__ float g_gcnt[NGRAPH];
__device__ __align__(128) uint2 g_wb[3][4096]; // W in mma B-fragment order

// ---------------------------------------------------------------------------
__global__ void k_zero(float* __restrict__ out, int N) {
    int i = blockIdx.x * blockDim.x + threadIdx.x;
    if (i < N) {
        g_cnt[i] = 0;
        #pragma unroll
        for (int r = 0; r < CREP; r++) g_cntR[r][i] = 0;
    }
    if (i < NGRAPH) g_gcnt[i] = 0.f;
    if (i < NGRAPH * D) out[i] = 0.f;
}

// pack all three W into mma B-fragment order (side stream)
__global__ void k_wconv(const float* __restrict__ W1,
                        const float* __restrict__ W2,
                        const float* __restrict__ W3) {
    int i = blockIdx.x * blockDim.x + threadIdx.x;
    if (i >= 3 * 4096) return;
    int layer = i >> 12;
    int idx = i & 4095;
    const float* W = layer == 0 ? W1 : (layer == 1 ? W2 : W3);
    int lane = idx & 31;
    int nt = (idx >> 5) & 15;
    int ks = idx >> 9;
    int tig = lane & 3, gid = lane >> 2;
    int n = nt * 8 + gid;
    int k0 = ks * 16 + tig * 2;
    __half2 b0 = __floats2half2_rn(W[k0 * D + n],       W[(k0 + 1) * D + n]);
    __half2 b1 = __floats2half2_rn(W[(k0 + 8) * D + n], W[(k0 + 9) * D + n]);
    g_wb[layer][idx] = make_uint2(*(unsigned*)&b0, *(unsigned*)&b1);
}

// count in-degree into replica (blockIdx&3): 8 edges per thread (2x int4)
__global__ void k_count8(const int4* __restrict__ dst4, int E4) {
    int* cnt = g_cntR[blockIdx.x & (CREP - 1)];
    int i = (blockIdx.x * blockDim.x + threadIdx.x) * 2;
    if (i < E4) {
        int4 e = __ldg(dst4 + i);
        atomicAdd(&cnt[e.x], 1);
        atomicAdd(&cnt[e.y], 1);
        atomicAdd(&cnt[e.z], 1);
        atomicAdd(&cnt[e.w], 1);
    }
    if (i + 1 < E4) {
        int4 e = __ldg(dst4 + i + 1);
        atomicAdd(&cnt[e.x], 1);
        atomicAdd(&cnt[e.y], 1);
        atomicAdd(&cnt[e.z], 1);
        atomicAdd(&cnt[e.w], 1);
    }
}
__global__ void k_count1(const int* __restrict__ dst, int E) {
    int e = blockIdx.x * blockDim.x + threadIdx.x;
    if (e < E) atomicAdd(&g_cntR[0][dst[e]], 1);
}

// ---------------------------------------------------------------------------
// scan1: warp-shuffle block scan over replica sums -> BLOCK-LOCAL g_off +
// g_bsum totals. Fused: dinv, per-graph counts. (g_cnt untouched: stays 0.)
__global__ void __launch_bounds__(SCAN_T)
k_scan1(const int* __restrict__ batch, int N) {
    __shared__ int wsum[32];
    int tid = threadIdx.x, lane = tid & 31, wid = tid >> 5;
    int base = blockIdx.x * SCAN_ELEMS + tid * SCAN_V;
    int v[SCAN_V];
    int sum = 0;
    #pragma unroll
    for (int k = 0; k < SCAN_V; k++) {
        int i = base + k;
        int c = 0;
        if (i < N) {
            #pragma unroll
            for (int r = 0; r < CREP; r++) c += g_cntR[r][i];
            g_dinv[i] = rsqrtf((float)(c + 1));
            atomicAdd(&g_gcnt[batch[i]], 1.f);
        }
        v[k] = c;
        sum += c;
    }
    int inc = sum;
    #pragma unroll
    for (int d2 = 1; d2 < 32; d2 <<= 1) {
        int t = __shfl_up_sync(0xffffffffu, inc, d2);
        if (lane >= d2) inc += t;
    }
    if (lane == 31) wsum[wid] = inc;
    __syncthreads();
    if (wid == 0) {
        int w = wsum[lane];
        #pragma unroll
        for (int d2 = 1; d2 < 32; d2 <<= 1) {
            int t = __shfl_up_sync(0xffffffffu, w, d2);
            if (lane >= d2) w += t;
        }
        wsum[lane] = w;
    }
    __syncthreads();
    int wprefix = (wid == 0) ? 0 : wsum[wid - 1];
    int excl = wprefix + inc - sum;
    #pragma unroll
    for (int k = 0; k < SCAN_V; k++) {
        int i = base + k;
        if (i < N) g_off[i] = excl;
        else if (i == N) g_off[N] = excl;
        excl += v[k];
    }
    if (tid == SCAN_T - 1) g_bsum[blockIdx.x] = wprefix + inc;
}

// Prolog helper (warp 0 only): exclusive prefix of g_bsum into s_pref[0..15].
__device__ __forceinline__ void load_bpref(int* s_pref, int nb) {
    if (threadIdx.x < 32) {
        int orig = ((int)threadIdx.x < nb) ? g_bsum[threadIdx.x] : 0;
        int v = orig;
        #pragma unroll
        for (int d2 = 1; d2 < 32; d2 <<= 1) {
            int t = __shfl_up_sync(0xffffffffu, v, d2);
            if ((int)threadIdx.x >= d2) v += t;
        }
        if (threadIdx.x < 16) s_pref[threadIdx.x] = v - orig;
    }
}

// scatter edges into CSR slots (prefix folded in)
__global__ void k_fill(const int* __restrict__ src,
                       const int* __restrict__ dst, int E, int nb) {
    __shared__ int s_pref[16];
    load_bpref(s_pref, nb);
    __syncthreads();
    int e = blockIdx.x * blockDim.x + threadIdx.x;
    if (e >= E) return;
    int d = dst[e];
    int s = src[e];
    int pos = g_off[d] + s_pref[d >> 12] + atomicAdd(&g_cnt[d], 1);
    float coef = g_dinv[s] * g_dinv[d];
    g_csr[pos] = make_int2(s, __float_as_int(coef));
}

// ---------------------------------------------------------------------------
// Tensor-core GEMM: h2[N,128](fp16) = X[N,128] @ W[128,128]
#define XS_STRIDE 136

__global__ void __launch_bounds__(256, 2)
k_gemm(const float* __restrict__ X0, int layer, int N, int use_x0) {
    __shared__ __half Xs[128 * XS_STRIDE];
    int tid = threadIdx.x;
    int lane = tid & 31, wid = tid >> 5;
    int row0 = blockIdx.x * 128;

    if (use_x0) {
        for (int i = tid; i < 128 * 32; i += 256) {
            int r = i >> 5, c4 = i & 31;
            int gr = row0 + r;
            float4 v = make_float4(0.f, 0.f, 0.f, 0.f);
            if (gr < N) v = __ldg((const float4*)(X0 + (size_t)gr * D) + c4);
            __half2 lo = __floats2half2_rn(v.x, v.y);
            __half2 hi = __floats2half2_rn(v.z, v.w);
            *(uint2*)&Xs[r * XS_STRIDE + c4 * 4] =
                make_uint2(*(unsigned*)&lo, *(unsigned*)&hi);
        }
    } else {
        for (int i = tid; i < 128 * 16; i += 256) {
            int r = i >> 4, c8 = i & 15;
            int gr = row0 + r;
            uint4 v = make_uint4(0u, 0u, 0u, 0u);
            if (gr < N) v = __ldg((const uint4*)(g_h1 + (size_t)gr * D) + c8);
            *(uint4*)&Xs[r * XS_STRIDE + c8 * 8] = v;
        }
    }
    __syncthreads();

    float acc[16][4];
    #pragma unroll
    for (int nt = 0; nt < 16; nt++)
        acc[nt][0] = acc[nt][1] = acc[nt][2] = acc[nt][3] = 0.f;

    int a_row = (lane & 7) | (((lane >> 3) & 1) << 3);
    int a_col8 = (lane >> 4) * 8;
    const __half* a_base = &Xs[(wid * 16 + a_row) * XS_STRIDE + a_col8];
    const uint2* Wb = g_wb[layer];

    #pragma unroll
    for (int ks = 0; ks < 8; ks++) {
        uint32_t a0, a1, a2, a3;
        uint32_t addr = (uint32_t)__cvta_generic_to_shared(a_base + ks * 16);
        asm volatile(
            "ldmatrix.sync.aligned.m8n8.x4.shared.b16 {%0,%1,%2,%3}, [%4];"
            : "=r"(a0), "=r"(a1), "=r"(a2), "=r"(a3) : "r"(addr));
        #pragma unroll
        for (int nt = 0; nt < 16; nt++) {
            uint2 b = __ldg(Wb + (ks * 16 + nt) * 32 + lane);
            asm volatile(
                "mma.sync.aligned.m16n8k16.row.col.f32.f16.f16.f32 "
                "{%0,%1,%2,%3},{%4,%5,%6,%7},{%8,%9},{%0,%1,%2,%3};"
                : "+f"(acc[nt][0]), "+f"(acc[nt][1]),
                  "+f"(acc[nt][2]), "+f"(acc[nt][3])
                : "r"(a0), "r"(a1), "r"(a2), "r"(a3), "r"(b.x), "r"(b.y));
        }
    }

    int tig = lane & 3, gid = lane >> 2;
    int r_lo = row0 + wid * 16 + gid;
    int r_hi = r_lo + 8;
    #pragma unroll
    for (int nt = 0; nt < 16; nt++) {
        int col = nt * 8 + tig * 2;
        if (r_lo < N) {
            __half2 h = __floats2half2_rn(acc[nt][0], acc[nt][1]);
            *(unsigned*)&g_h2[(size_t)r_lo * D + col] = *(unsigned*)&h;
        }
        if (r_hi < N) {
            __half2 h = __floats2half2_rn(acc[nt][2], acc[nt][3]);
            *(unsigned*)&g_h2[(size_t)r_hi * D + col] = *(unsigned*)&h;
        }
    }
}

// ---------------------------------------------------------------------------
// Aggregation (proven loop body): warp per node, lane covers 4 cols.
// Gather loads use __ldcg (L2-only): random rows have ~0% L1 hit rate and
// only thrash L1 for the sequential CSR/bias streams.
__device__ __forceinline__ void agg_edge(float4& acc, const __half* T,
                                         int s, float c, int lane) {
    uint2 p = __ldcg((const uint2*)(T + (size_t)s * D) + lane);
    float2 v0 = __half22float2(*(const __half2*)&p.x);
    float2 v1 = __half22float2(*(const __half2*)&p.y);
    acc.x = fmaf(c, v0.x, acc.x);
    acc.y = fmaf(c, v0.y, acc.y);
    acc.z = fmaf(c, v1.x, acc.z);
    acc.w = fmaf(c, v1.y, acc.w);
}

__device__ __forceinline__ float4 agg_node(const float* __restrict__ bias,
                                           int n, int lane, int j, int end) {
    const __half* T = g_h2;
    float di = g_dinv[n];
    float cs = di * di;
    float4 acc = make_float4(0.f, 0.f, 0.f, 0.f);
    agg_edge(acc, T, n, cs, lane);   // self-loop

    for (; j + 4 <= end; j += 4) {
        int2 e0 = g_csr[j + 0];
        int2 e1 = g_csr[j + 1];
        int2 e2 = g_csr[j + 2];
        int2 e3 = g_csr[j + 3];
        agg_edge(acc, T, e0.x, __int_as_float(e0.y), lane);
        agg_edge(acc, T, e1.x, __int_as_float(e1.y), lane);
        agg_edge(acc, T, e2.x, __int_as_float(e2.y), lane);
        agg_edge(acc, T, e3.x, __int_as_float(e3.y), lane);
    }
    for (; j < end; j++) {
        int2 e = g_csr[j];
        agg_edge(acc, T, e.x, __int_as_float(e.y), lane);
    }

    float4 b = __ldg((const float4*)bias + lane);
    acc.x = fmaxf(acc.x + b.x, 0.f);
    acc.y = fmaxf(acc.y + b.y, 0.f);
    acc.z = fmaxf(acc.z + b.z, 0.f);
    acc.w = fmaxf(acc.w + b.w, 0.f);
    return acc;
}

// layers 1-2: write h1 (fp16)
__global__ void __launch_bounds__(256)
k_agg(const float* __restrict__ bias, int N, int nb) {
    __shared__ int s_pref[16];
    load_bpref(s_pref, nb);
    __syncthreads();
    int warp = (blockIdx.x * blockDim.x + threadIdx.x) >> 5;
    int lane = threadIdx.x & 31;
    if (warp >= N) return;
    int j   = g_off[warp]     + s_pref[warp >> 12];
    int end = g_off[warp + 1] + s_pref[(warp + 1) >> 12];
    float4 acc = agg_node(bias, warp, lane, j, end);
    __half2 lo = __floats2half2_rn(acc.x, acc.y);
    __half2 hi = __floats2half2_rn(acc.z, acc.w);
    *(uint2*)(g_h1 + (size_t)warp * D + lane * 4) =
        make_uint2(*(unsigned*)&lo, *(unsigned*)&hi);
}

// layer 3 + pool: sorted-batch leader reduction, then per-segment atomics
__global__ void __launch_bounds__(256)
k_agg_pool(const float* __restrict__ bias, const int* __restrict__ batch,
           float* __restrict__ out, int N, int nb) {
    __shared__ int s_pref[16];
    __shared__ int s_g[8];
    __shared__ float s_acc[8 * 128];
    load_bpref(s_pref, nb);
    __syncthreads();
    int tid = threadIdx.x;
    int wid = tid >> 5, lane = tid & 31;
    int warp = (blockIdx.x * blockDim.x + tid) >> 5;
    bool valid = warp < N;

    float4 acc = make_float4(0.f, 0.f, 0.f, 0.f);
    int g = -1;
    if (valid) {
        int j   = g_off[warp]     + s_pref[warp >> 12];
        int end = g_off[warp + 1] + s_pref[(warp + 1) >> 12];
        acc = agg_node(bias, warp, lane, j, end);
        g = batch[warp];
    }
    if (lane == 0) s_g[wid] = g;
    *(float4*)&s_acc[wid * 128 + lane * 4] = acc;
    __syncthreads();

    int myg = s_g[wid];
    bool leader = (myg >= 0) && (wid == 0 || s_g[wid - 1] != myg);
    if (leader) {
        float4 sum = *(float4*)&s_acc[wid * 128 + lane * 4];
        for (int w = wid + 1; w < 8 && s_g[w] == myg; w++) {
            float4 t = *(float4*)&s_acc[w * 128 + lane * 4];
            sum.x += t.x; sum.y += t.y; sum.z += t.z; sum.w += t.w;
        }
        float* o = out + (size_t)myg * D + lane * 4;
        atomicAdd(o + 0, sum.x);
        atomicAdd(o + 1, sum.y);
        atomicAdd(o + 2, sum.z);
        atomicAdd(o + 3, sum.w);
    }
}

__global__ void k_div(float* __restrict__ out) {
    int i = blockIdx.x * blockDim.x + threadIdx.x;
    if (i < NGRAPH * D) out[i] = out[i] / fmaxf(g_gcnt[i >> 7], 1.f);
}

// ---------------------------------------------------------------------------
extern "C" void kernel_launch(void* const* d_in, const int* in_sizes, int n_in,
                              void* d_out, int out_size) {
    const float* x  = (const float*)d_in[0];
    // d_in[1] = edge_attr (unused)
    const float* W1 = (const float*)d_in[2];
    const float* b1 = (const float*)d_in[3];
    const float* W2 = (const float*)d_in[4];
    const float* b2 = (const float*)d_in[5];
    const float* W3 = (const float*)d_in[6];
    const float* b3 = (const float*)d_in[7];
    const int* ei    = (const int*)d_in[8];
    const int* batch = (const int*)d_in[9];
    float* out = (float*)d_out;

    int N = in_sizes[0] / D;
    int E = in_sizes[8] / 2;
    const int* src = ei;
    const int* dst = ei + E;

    int span = N > NGRAPH * D ? N : NGRAPH * D;
    int initb = (span + 255) / 256;
    int eb = (E + 255) / 256;
    int gb = (N + 127) / 128;
    int ab = ((N * 32) + 255) / 256;
    int sb = (N + SCAN_ELEMS - 1) / SCAN_ELEMS;

    // side stream: {wconv, gemm1} overlap the CSR build on the main stream.
    cudaStream_t s2;
    cudaStreamCreateWithFlags(&s2, cudaStreamNonBlocking);
    cudaEvent_t evF, evJ;
    cudaEventCreateWithFlags(&evF, cudaEventDisableTiming);
    cudaEventCreateWithFlags(&evJ, cudaEventDisableTiming);

    cudaEventRecord(evF, 0);
    cudaStreamWaitEvent(s2, evF, 0);
    k_wconv<<<48, 256, 0, s2>>>(W1, W2, W3);
    k_gemm<<<gb, 256, 0, s2>>>(x, 0, N, 1);        // layer-1 GEMM -> g_h2
    cudaEventRecord(evJ, s2);

    // main stream: CSR build (replicated count)
    k_zero<<<initb, 256>>>(out, N);
    bool vec4 = (E % 4 == 0) && ((((uintptr_t)dst) & 15) == 0);
    if (vec4) {
        int E4 = E / 4;
        int nt = (E4 + 1) / 2;
        k_count8<<<(nt + 255) / 256, 256>>>((const int4*)dst, E4);
    } else {
        k_count1<<<eb, 256>>>(dst, E);
    }
    k_scan1<<<sb, SCAN_T>>>(batch, N);
    k_fill<<<eb, 256>>>(src, dst, E, sb);

    // join: agg needs both g_h2 (s2) and CSR (main)
    cudaStreamWaitEvent(0, evJ, 0);

    // layer 1 agg: h2 -> h1
    k_agg<<<ab, 256>>>(b1, N, sb);
    // layer 2: h1 -> h2 -> h1
    k_gemm<<<gb, 256>>>(x, 1, N, 0);
    k_agg<<<ab, 256>>>(b2, N, sb);
    // layer 3: h1 -> h2 -> out (leader-reduced pool)
    k_gemm<<<gb, 256>>>(x, 2, N, 0);
    k_agg_pool<<<ab, 256>>>(b3, batch, out, N, sb);

    k_div<<<(NGRAPH * D + 255) / 256, 256>>>(out);
}

// round 16
// speedup vs baseline: 1.0226x; 1.0226x over previous
#include <cuda_runtime.h>
#include <cuda_fp16.h>
#include <cstdint>

// ---------------------------------------------------------------------------
// GraphBackboneGCN: 3x (GCNConv + ReLU) + global mean pool.
// R16: R13 base (ldcg reverted; __ldg gather proven best) + self-cleaning
//      counters: scan1 re-zeros g_cntR/g_cnt for the next replay, so k_zero
//      only touches out+gcnt. Module-load zero-init covers the first run.
// ---------------------------------------------------------------------------

#define NMAX 50176
#define EMAX 1048576
#define D 128
#define NGRAPH 512
#define CREP 4

#define SCAN_T 1024
#define SCAN_V 4
#define SCAN_ELEMS (SCAN_T * SCAN_V)   // 4096 = 1<<12

__device__ __align__(128) __half g_h1[(size_t)NMAX * D];   // agg out (fp16)
__device__ __align__(128) __half g_h2[(size_t)NMAX * D];   // gemm out / gather src
__device__ float g_dinv[NMAX];
__device__ int   g_cnt[NMAX];                  // fill cursor (scan1-cleaned)
__device__ int   g_cntR[CREP][NMAX];           // replicated count (scan1-cleaned)
__device__ int   g_off[NMAX + 1];              // block-LOCAL exclusive offsets
__device__ int   g_bsum[64];                   // per-scan1-block totals
__device__ __align__(128) int2 g_csr[EMAX];    // .x = src, .y = coef bits
__device__ float g_gcnt[NGRAPH];
__device__ __align__(128) uint2 g_wb[3][4096]; // W in mma B-fragment order

// ---------------------------------------------------------------------------
// zero only out + per-graph counts (counters are cleaned by scan1 each launch)
__global__ void k_zero(float* __restrict__ out) {
    int i = blockIdx.x * blockDim.x + threadIdx.x;
    if (i < NGRAPH) g_gcnt[i] = 0.f;
    if (i < NGRAPH * D) out[i] = 0.f;
}

// pack all three W into mma B-fragment order (side stream)
__global__ void k_wconv(const float* __restrict__ W1,
                        const float* __restrict__ W2,
                        const float* __restrict__ W3) {
    int i = blockIdx.x * blockDim.x + threadIdx.x;
    if (i >= 3 * 4096) return;
    int layer = i >> 12;
    int idx = i & 4095;
    const float* W = layer == 0 ? W1 : (layer == 1 ? W2 : W3);
    int lane = idx & 31;
    int nt = (idx >> 5) & 15;
    int ks = idx >> 9;
    int tig = lane & 3, gid = lane >> 2;
    int n = nt * 8 + gid;
    int k0 = ks * 16 + tig * 2;
    __half2 b0 = __floats2half2_rn(W[k0 * D + n],       W[(k0 + 1) * D + n]);
    __half2 b1 = __floats2half2_rn(W[(k0 + 8) * D + n], W[(k0 + 9) * D + n]);
    g_wb[layer][idx] = make_uint2(*(unsigned*)&b0, *(unsigned*)&b1);
}

// count in-degree into replica (blockIdx&3): 8 edges per thread (2x int4)
__global__ void k_count8(const int4* __restrict__ dst4, int E4) {
    int* cnt = g_cntR[blockIdx.x & (CREP - 1)];
    int i = (blockIdx.x * blockDim.x + threadIdx.x) * 2;
    if (i < E4) {
        int4 e = __ldg(dst4 + i);
        atomicAdd(&cnt[e.x], 1);
        atomicAdd(&cnt[e.y], 1);
        atomicAdd(&cnt[e.z], 1);
        atomicAdd(&cnt[e.w], 1);
    }
    if (i + 1 < E4) {
        int4 e = __ldg(dst4 + i + 1);
        atomicAdd(&cnt[e.x], 1);
        atomicAdd(&cnt[e.y], 1);
        atomicAdd(&cnt[e.z], 1);
        atomicAdd(&cnt[e.w], 1);
    }
}
__global__ void k_count1(const int* __restrict__ dst, int E) {
    int e = blockIdx.x * blockDim.x + threadIdx.x;
    if (e < E) atomicAdd(&g_cntR[0][dst[e]], 1);
}

// ---------------------------------------------------------------------------
// scan1: warp-shuffle block scan over replica sums -> BLOCK-LOCAL g_off +
// g_bsum. Fused: dinv, per-graph counts, counter cleaning for next replay.
__global__ void __launch_bounds__(SCAN_T)
k_scan1(const int* __restrict__ batch, int N) {
    __shared__ int wsum[32];
    int tid = threadIdx.x, lane = tid & 31, wid = tid >> 5;
    int base = blockIdx.x * SCAN_ELEMS + tid * SCAN_V;
    int v[SCAN_V];
    int sum = 0;
    #pragma unroll
    for (int k = 0; k < SCAN_V; k++) {
        int i = base + k;
        int c = 0;
        if (i < N) {
            #pragma unroll
            for (int r = 0; r < CREP; r++) {
                c += g_cntR[r][i];
                g_cntR[r][i] = 0;          // clean for next replay
            }
            g_cnt[i] = 0;                  // fill cursor reset
            g_dinv[i] = rsqrtf((float)(c + 1));
            atomicAdd(&g_gcnt[batch[i]], 1.f);
        }
        v[k] = c;
        sum += c;
    }
    int inc = sum;
    #pragma unroll
    for (int d2 = 1; d2 < 32; d2 <<= 1) {
        int t = __shfl_up_sync(0xffffffffu, inc, d2);
        if (lane >= d2) inc += t;
    }
    if (lane == 31) wsum[wid] = inc;
    __syncthreads();
    if (wid == 0) {
        int w = wsum[lane];
        #pragma unroll
        for (int d2 = 1; d2 < 32; d2 <<= 1) {
            int t = __shfl_up_sync(0xffffffffu, w, d2);
            if (lane >= d2) w += t;
        }
        wsum[lane] = w;
    }
    __syncthreads();
    int wprefix = (wid == 0) ? 0 : wsum[wid - 1];
    int excl = wprefix + inc - sum;
    #pragma unroll
    for (int k = 0; k < SCAN_V; k++) {
        int i = base + k;
        if (i < N) g_off[i] = excl;
        else if (i == N) g_off[N] = excl;
        excl += v[k];
    }
    if (tid == SCAN_T - 1) g_bsum[blockIdx.x] = wprefix + inc;
}

// Prolog helper (warp 0 only): exclusive prefix of g_bsum into s_pref[0..15].
__device__ __forceinline__ void load_bpref(int* s_pref, int nb) {
    if (threadIdx.x < 32) {
        int orig = ((int)threadIdx.x < nb) ? g_bsum[threadIdx.x] : 0;
        int v = orig;
        #pragma unroll
        for (int d2 = 1; d2 < 32; d2 <<= 1) {
            int t = __shfl_up_sync(0xffffffffu, v, d2);
            if ((int)threadIdx.x >= d2) v += t;
        }
        if (threadIdx.x < 16) s_pref[threadIdx.x] = v - orig;
    }
}

// scatter edges into CSR slots (prefix folded in)
__global__ void k_fill(const int* __restrict__ src,
                       const int* __restrict__ dst, int E, int nb) {
    __shared__ int s_pref[16];
    load_bpref(s_pref, nb);
    __syncthreads();
    int e = blockIdx.x * blockDim.x + threadIdx.x;
    if (e >= E) return;
    int d = dst[e];
    int s = src[e];
    int pos = g_off[d] + s_pref[d >> 12] + atomicAdd(&g_cnt[d], 1);
    float coef = g_dinv[s] * g_dinv[d];
    g_csr[pos] = make_int2(s, __float_as_int(coef));
}

// ---------------------------------------------------------------------------
// Tensor-core GEMM: h2[N,128](fp16) = X[N,128] @ W[128,128]
#define XS_STRIDE 136

__global__ void __launch_bounds__(256, 2)
k_gemm(const float* __restrict__ X0, int layer, int N, int use_x0) {
    __shared__ __half Xs[128 * XS_STRIDE];
    int tid = threadIdx.x;
    int lane = tid & 31, wid = tid >> 5;
    int row0 = blockIdx.x * 128;

    if (use_x0) {
        for (int i = tid; i < 128 * 32; i += 256) {
            int r = i >> 5, c4 = i & 31;
            int gr = row0 + r;
            float4 v = make_float4(0.f, 0.f, 0.f, 0.f);
            if (gr < N) v = __ldg((const float4*)(X0 + (size_t)gr * D) + c4);
            __half2 lo = __floats2half2_rn(v.x, v.y);
            __half2 hi = __floats2half2_rn(v.z, v.w);
            *(uint2*)&Xs[r * XS_STRIDE + c4 * 4] =
                make_uint2(*(unsigned*)&lo, *(unsigned*)&hi);
        }
    } else {
        for (int i = tid; i < 128 * 16; i += 256) {
            int r = i >> 4, c8 = i & 15;
            int gr = row0 + r;
            uint4 v = make_uint4(0u, 0u, 0u, 0u);
            if (gr < N) v = __ldg((const uint4*)(g_h1 + (size_t)gr * D) + c8);
            *(uint4*)&Xs[r * XS_STRIDE + c8 * 8] = v;
        }
    }
    __syncthreads();

    float acc[16][4];
    #pragma unroll
    for (int nt = 0; nt < 16; nt++)
        acc[nt][0] = acc[nt][1] = acc[nt][2] = acc[nt][3] = 0.f;

    int a_row = (lane & 7) | (((lane >> 3) & 1) << 3);
    int a_col8 = (lane >> 4) * 8;
    const __half* a_base = &Xs[(wid * 16 + a_row) * XS_STRIDE + a_col8];
    const uint2* Wb = g_wb[layer];

    #pragma unroll
    for (int ks = 0; ks < 8; ks++) {
        uint32_t a0, a1, a2, a3;
        uint32_t addr = (uint32_t)__cvta_generic_to_shared(a_base + ks * 16);
        asm volatile(
            "ldmatrix.sync.aligned.m8n8.x4.shared.b16 {%0,%1,%2,%3}, [%4];"
            : "=r"(a0), "=r"(a1), "=r"(a2), "=r"(a3) : "r"(addr));
        #pragma unroll
        for (int nt = 0; nt < 16; nt++) {
            uint2 b = __ldg(Wb + (ks * 16 + nt) * 32 + lane);
            asm volatile(
                "mma.sync.aligned.m16n8k16.row.col.f32.f16.f16.f32 "
                "{%0,%1,%2,%3},{%4,%5,%6,%7},{%8,%9},{%0,%1,%2,%3};"
                : "+f"(acc[nt][0]), "+f"(acc[nt][1]),
                  "+f"(acc[nt][2]), "+f"(acc[nt][3])
                : "r"(a0), "r"(a1), "r"(a2), "r"(a3), "r"(b.x), "r"(b.y));
        }
    }

    int tig = lane & 3, gid = lane >> 2;
    int r_lo = row0 + wid * 16 + gid;
    int r_hi = r_lo + 8;
    #pragma unroll
    for (int nt = 0; nt < 16; nt++) {
        int col = nt * 8 + tig * 2;
        if (r_lo < N) {
            __half2 h = __floats2half2_rn(acc[nt][0], acc[nt][1]);
            *(unsigned*)&g_h2[(size_t)r_lo * D + col] = *(unsigned*)&h;
        }
        if (r_hi < N) {
            __half2 h = __floats2half2_rn(acc[nt][2], acc[nt][3]);
            *(unsigned*)&g_h2[(size_t)r_hi * D + col] = *(unsigned*)&h;
        }
    }
}

// ---------------------------------------------------------------------------
// Aggregation (proven loop body): warp per node, lane covers 4 cols, __ldg.
__device__ __forceinline__ void agg_edge(float4& acc, const __half* T,
                                         int s, float c, int lane) {
    uint2 p = __ldg((const uint2*)(T + (size_t)s * D) + lane);
    float2 v0 = __half22float2(*(const __half2*)&p.x);
    float2 v1 = __half22float2(*(const __half2*)&p.y);
    acc.x = fmaf(c, v0.x, acc.x);
    acc.y = fmaf(c, v0.y, acc.y);
    acc.z = fmaf(c, v1.x, acc.z);
    acc.w = fmaf(c, v1.y, acc.w);
}

__device__ __forceinline__ float4 agg_node(const float* __restrict__ bias,
                                           int n, int lane, int j, int end) {
    const __half* T = g_h2;
    float di = g_dinv[n];
    float cs = di * di;
    float4 acc = make_float4(0.f, 0.f, 0.f, 0.f);
    agg_edge(acc, T, n, cs, lane);   // self-loop

    for (; j + 4 <= end; j += 4) {
        int2 e0 = g_csr[j + 0];
        int2 e1 = g_csr[j + 1];
        int2 e2 = g_csr[j + 2];
        int2 e3 = g_csr[j + 3];
        agg_edge(acc, T, e0.x, __int_as_float(e0.y), lane);
        agg_edge(acc, T, e1.x, __int_as_float(e1.y), lane);
        agg_edge(acc, T, e2.x, __int_as_float(e2.y), lane);
        agg_edge(acc, T, e3.x, __int_as_float(e3.y), lane);
    }
    for (; j < end; j++) {
        int2 e = g_csr[j];
        agg_edge(acc, T, e.x, __int_as_float(e.y), lane);
    }

    float4 b = __ldg((const float4*)bias + lane);
    acc.x = fmaxf(acc.x + b.x, 0.f);
    acc.y = fmaxf(acc.y + b.y, 0.f);
    acc.z = fmaxf(acc.z + b.z, 0.f);
    acc.w = fmaxf(acc.w + b.w, 0.f);
    return acc;
}

// layers 1-2: write h1 (fp16)
__global__ void __launch_bounds__(256)
k_agg(const float* __restrict__ bias, int N, int nb) {
    __shared__ int s_pref[16];
    load_bpref(s_pref, nb);
    __syncthreads();
    int warp = (blockIdx.x * blockDim.x + threadIdx.x) >> 5;
    int lane = threadIdx.x & 31;
    if (warp >= N) return;
    int j   = g_off[warp]     + s_pref[warp >> 12];
    int end = g_off[warp + 1] + s_pref[(warp + 1) >> 12];
    float4 acc = agg_node(bias, warp, lane, j, end);
    __half2 lo = __floats2half2_rn(acc.x, acc.y);
    __half2 hi = __floats2half2_rn(acc.z, acc.w);
    *(uint2*)(g_h1 + (size_t)warp * D + lane * 4) =
        make_uint2(*(unsigned*)&lo, *(unsigned*)&hi);
}

// layer 3 + pool: sorted-batch leader reduction, then per-segment atomics
__global__ void __launch_bounds__(256)
k_agg_pool(const float* __restrict__ bias, const int* __restrict__ batch,
           float* __restrict__ out, int N, int nb) {
    __shared__ int s_pref[16];
    __shared__ int s_g[8];
    __shared__ float s_acc[8 * 128];
    load_bpref(s_pref, nb);
    __syncthreads();
    int tid = threadIdx.x;
    int wid = tid >> 5, lane = tid & 31;
    int warp = (blockIdx.x * blockDim.x + tid) >> 5;
    bool valid = warp < N;

    float4 acc = make_float4(0.f, 0.f, 0.f, 0.f);
    int g = -1;
    if (valid) {
        int j   = g_off[warp]     + s_pref[warp >> 12];
        int end = g_off[warp + 1] + s_pref[(warp + 1) >> 12];
        acc = agg_node(bias, warp, lane, j, end);
        g = batch[warp];
    }
    if (lane == 0) s_g[wid] = g;
    *(float4*)&s_acc[wid * 128 + lane * 4] = acc;
    __syncthreads();

    int myg = s_g[wid];
    bool leader = (myg >= 0) && (wid == 0 || s_g[wid - 1] != myg);
    if (leader) {
        float4 sum = *(float4*)&s_acc[wid * 128 + lane * 4];
        for (int w = wid + 1; w < 8 && s_g[w] == myg; w++) {
            float4 t = *(float4*)&s_acc[w * 128 + lane * 4];
            sum.x += t.x; sum.y += t.y; sum.z += t.z; sum.w += t.w;
        }
        float* o = out + (size_t)myg * D + lane * 4;
        atomicAdd(o + 0, sum.x);
        atomicAdd(o + 1, sum.y);
        atomicAdd(o + 2, sum.z);
        atomicAdd(o + 3, sum.w);
    }
}

__global__ void k_div(float* __restrict__ out) {
    int i = blockIdx.x * blockDim.x + threadIdx.x;
    if (i < NGRAPH * D) out[i] = out[i] / fmaxf(g_gcnt[i >> 7], 1.f);
}

// ---------------------------------------------------------------------------
extern "C" void kernel_launch(void* const* d_in, const int* in_sizes, int n_in,
                              void* d_out, int out_size) {
    const float* x  = (const float*)d_in[0];
    // d_in[1] = edge_attr (unused)
    const float* W1 = (const float*)d_in[2];
    const float* b1 = (const float*)d_in[3];
    const float* W2 = (const float*)d_in[4];
    const float* b2 = (const float*)d_in[5];
    const float* W3 = (const float*)d_in[6];
    const float* b3 = (const float*)d_in[7];
    const int* ei    = (const int*)d_in[8];
    const int* batch = (const int*)d_in[9];
    float* out = (float*)d_out;

    int N = in_sizes[0] / D;
    int E = in_sizes[8] / 2;
    const int* src = ei;
    const int* dst = ei + E;

    int eb = (E + 255) / 256;
    int gb = (N + 127) / 128;
    int ab = ((N * 32) + 255) / 256;
    int sb = (N + SCAN_ELEMS - 1) / SCAN_ELEMS;

    // side stream: {wconv, gemm1} overlap the CSR build on the main stream.
    cudaStream_t s2;
    cudaStreamCreateWithFlags(&s2, cudaStreamNonBlocking);
    cudaEvent_t evF, evJ;
    cudaEventCreateWithFlags(&evF, cudaEventDisableTiming);
    cudaEventCreateWithFlags(&evJ, cudaEventDisableTiming);

    cudaEventRecord(evF, 0);
    cudaStreamWaitEvent(s2, evF, 0);
    k_wconv<<<48, 256, 0, s2>>>(W1, W2, W3);
    k_gemm<<<gb, 256, 0, s2>>>(x, 0, N, 1);        // layer-1 GEMM -> g_h2
    cudaEventRecord(evJ, s2);

    // main stream: CSR build (counters pre-cleaned by previous launch's scan1;
    // module-load zero-init covers the very first execution)
    k_zero<<<(NGRAPH * D + 255) / 256, 256>>>(out);
    bool vec4 = (E % 4 == 0) && ((((uintptr_t)dst) & 15) == 0);
    if (vec4) {
        int E4 = E / 4;
        int nt = (E4 + 1) / 2;
        k_count8<<<(nt + 255) / 256, 256>>>((const int4*)dst, E4);
    } else {
        k_count1<<<eb, 256>>>(dst, E);
    }
    k_scan1<<<sb, SCAN_T>>>(batch, N);
    k_fill<<<eb, 256>>>(src, dst, E, sb);

    // join: agg needs both g_h2 (s2) and CSR (main)
    cudaStreamWaitEvent(0, evJ, 0);

    // layer 1 agg: h2 -> h1
    k_agg<<<ab, 256>>>(b1, N, sb);
    // layer 2: h1 -> h2 -> h1
    k_gemm<<<gb, 256>>>(x, 1, N, 0);
    k_agg<<<ab, 256>>>(b2, N, sb);
    // layer 3: h1 -> h2 -> out (leader-reduced pool)
    k_gemm<<<gb, 256>>>(x, 2, N, 0);
    k_agg_pool<<<ab, 256>>>(b3, batch, out, N, sb);

    k_div<<<(NGRAPH * D + 255) / 256, 256>>>(out);
}

// round 17
// speedup vs baseline: 1.0336x; 1.0107x over previous
#include <cuda_runtime.h>
#include <cuda_fp16.h>
#include <cstdint>

// ---------------------------------------------------------------------------
// GraphBackboneGCN: 3x (GCNConv + ReLU) + global mean pool.
// FINAL (== R13, session best 161.4us):
//   - HMMA m16n8k16 GEMM, W pre-packed to B-fragment order (L1-hot LDG.64)
//   - fp16 hidden buffers; warp-per-node uint2 gather aggregation (__ldg)
//   - CSR via 4-way replicated count histogram + warp-shuffle scan
//     (block-local offsets; consumers fold the <=13 block prefixes in-warp)
//   - stream-forked {wconv, gemm1} overlapping the CSR build
//   - layer-3 aggregation fused with sorted-batch leader-reduced mean-pool
// Probes measured and rejected: ldcg gather (+5.0), half-warp agg (+46),
// agg+GEMM fusion (+98), 8-edge unroll/replica fill (+1.5), self-clean (+1.4).
// ---------------------------------------------------------------------------

#define NMAX 50176
#define EMAX 1048576
#define D 128
#define NGRAPH 512
#define CREP 4

#define SCAN_T 1024
#define SCAN_V 4
#define SCAN_ELEMS (SCAN_T * SCAN_V)   // 4096 = 1<<12

__device__ __align__(128) __half g_h1[(size_t)NMAX * D];   // agg out (fp16)
__device__ __align__(128) __half g_h2[(size_t)NMAX * D];   // gemm out / gather src
__device__ float g_dinv[NMAX];
__device__ int   g_cnt[NMAX];                  // fill cursor (zeroed once)
__device__ int   g_cntR[CREP][NMAX];           // replicated count histogram
__device__ int   g_off[NMAX + 1];              // block-LOCAL exclusive offsets
__device__ int   g_bsum[64];                   // per-scan1-block totals
__device__ __align__(128) int2 g_csr[EMAX];    // .x = src, .y = coef bits
__device__ float g_gcnt[NGRAPH];
__device__ __align__(128) uint2 g_wb[3][4096]; // W in mma B-fragment order

// ---------------------------------------------------------------------------
__global__ void k_zero(float* __restrict__ out, int N) {
    int i = blockIdx.x * blockDim.x + threadIdx.x;
    if (i < N) {
        g_cnt[i] = 0;
        #pragma unroll
        for (int r = 0; r < CREP; r++) g_cntR[r][i] = 0;
    }
    if (i < NGRAPH) g_gcnt[i] = 0.f;
    if (i < NGRAPH * D) out[i] = 0.f;
}

// pack all three W into mma B-fragment order (side stream)
__global__ void k_wconv(const float* __restrict__ W1,
                        const float* __restrict__ W2,
                        const float* __restrict__ W3) {
    int i = blockIdx.x * blockDim.x + threadIdx.x;
    if (i >= 3 * 4096) return;
    int layer = i >> 12;
    int idx = i & 4095;
    const float* W = layer == 0 ? W1 : (layer == 1 ? W2 : W3);
    int lane = idx & 31;
    int nt = (idx >> 5) & 15;
    int ks = idx >> 9;
    int tig = lane & 3, gid = lane >> 2;
    int n = nt * 8 + gid;
    int k0 = ks * 16 + tig * 2;
    __half2 b0 = __floats2half2_rn(W[k0 * D + n],       W[(k0 + 1) * D + n]);
    __half2 b1 = __floats2half2_rn(W[(k0 + 8) * D + n], W[(k0 + 9) * D + n]);
    g_wb[layer][idx] = make_uint2(*(unsigned*)&b0, *(unsigned*)&b1);
}

// count in-degree into replica (blockIdx&3): 8 edges per thread (2x int4)
__global__ void k_count8(const int4* __restrict__ dst4, int E4) {
    int* cnt = g_cntR[blockIdx.x & (CREP - 1)];
    int i = (blockIdx.x * blockDim.x + threadIdx.x) * 2;
    if (i < E4) {
        int4 e = __ldg(dst4 + i);
        atomicAdd(&cnt[e.x], 1);
        atomicAdd(&cnt[e.y], 1);
        atomicAdd(&cnt[e.z], 1);
        atomicAdd(&cnt[e.w], 1);
    }
    if (i + 1 < E4) {
        int4 e = __ldg(dst4 + i + 1);
        atomicAdd(&cnt[e.x], 1);
        atomicAdd(&cnt[e.y], 1);
        atomicAdd(&cnt[e.z], 1);
        atomicAdd(&cnt[e.w], 1);
    }
}
__global__ void k_count1(const int* __restrict__ dst, int E) {
    int e = blockIdx.x * blockDim.x + threadIdx.x;
    if (e < E) atomicAdd(&g_cntR[0][dst[e]], 1);
}

// ---------------------------------------------------------------------------
// scan1: warp-shuffle block scan over replica sums -> BLOCK-LOCAL g_off +
// g_bsum totals. Fused: dinv, per-graph counts. (g_cnt untouched: stays 0.)
__global__ void __launch_bounds__(SCAN_T)
k_scan1(const int* __restrict__ batch, int N) {
    __shared__ int wsum[32];
    int tid = threadIdx.x, lane = tid & 31, wid = tid >> 5;
    int base = blockIdx.x * SCAN_ELEMS + tid * SCAN_V;
    int v[SCAN_V];
    int sum = 0;
    #pragma unroll
    for (int k = 0; k < SCAN_V; k++) {
        int i = base + k;
        int c = 0;
        if (i < N) {
            #pragma unroll
            for (int r = 0; r < CREP; r++) c += g_cntR[r][i];
            g_dinv[i] = rsqrtf((float)(c + 1));
            atomicAdd(&g_gcnt[batch[i]], 1.f);
        }
        v[k] = c;
        sum += c;
    }
    int inc = sum;
    #pragma unroll
    for (int d2 = 1; d2 < 32; d2 <<= 1) {
        int t = __shfl_up_sync(0xffffffffu, inc, d2);
        if (lane >= d2) inc += t;
    }
    if (lane == 31) wsum[wid] = inc;
    __syncthreads();
    if (wid == 0) {
        int w = wsum[lane];
        #pragma unroll
        for (int d2 = 1; d2 < 32; d2 <<= 1) {
            int t = __shfl_up_sync(0xffffffffu, w, d2);
            if (lane >= d2) w += t;
        }
        wsum[lane] = w;
    }
    __syncthreads();
    int wprefix = (wid == 0) ? 0 : wsum[wid - 1];
    int excl = wprefix + inc - sum;
    #pragma unroll
    for (int k = 0; k < SCAN_V; k++) {
        int i = base + k;
        if (i < N) g_off[i] = excl;
        else if (i == N) g_off[N] = excl;
        excl += v[k];
    }
    if (tid == SCAN_T - 1) g_bsum[blockIdx.x] = wprefix + inc;
}

// Prolog helper (warp 0 only): exclusive prefix of g_bsum into s_pref[0..15].
__device__ __forceinline__ void load_bpref(int* s_pref, int nb) {
    if (threadIdx.x < 32) {
        int orig = ((int)threadIdx.x < nb) ? g_bsum[threadIdx.x] : 0;
        int v = orig;
        #pragma unroll
        for (int d2 = 1; d2 < 32; d2 <<= 1) {
            int t = __shfl_up_sync(0xffffffffu, v, d2);
            if ((int)threadIdx.x >= d2) v += t;
        }
        if (threadIdx.x < 16) s_pref[threadIdx.x] = v - orig;
    }
}

// scatter edges into CSR slots (prefix folded in)
__global__ void k_fill(const int* __restrict__ src,
                       const int* __restrict__ dst, int E, int nb) {
    __shared__ int s_pref[16];
    load_bpref(s_pref, nb);
    __syncthreads();
    int e = blockIdx.x * blockDim.x + threadIdx.x;
    if (e >= E) return;
    int d = dst[e];
    int s = src[e];
    int pos = g_off[d] + s_pref[d >> 12] + atomicAdd(&g_cnt[d], 1);
    float coef = g_dinv[s] * g_dinv[d];
    g_csr[pos] = make_int2(s, __float_as_int(coef));
}

// ---------------------------------------------------------------------------
// Tensor-core GEMM: h2[N,128](fp16) = X[N,128] @ W[128,128]
#define XS_STRIDE 136

__global__ void __launch_bounds__(256, 2)
k_gemm(const float* __restrict__ X0, int layer, int N, int use_x0) {
    __shared__ __half Xs[128 * XS_STRIDE];
    int tid = threadIdx.x;
    int lane = tid & 31, wid = tid >> 5;
    int row0 = blockIdx.x * 128;

    if (use_x0) {
        for (int i = tid; i < 128 * 32; i += 256) {
            int r = i >> 5, c4 = i & 31;
            int gr = row0 + r;
            float4 v = make_float4(0.f, 0.f, 0.f, 0.f);
            if (gr < N) v = __ldg((const float4*)(X0 + (size_t)gr * D) + c4);
            __half2 lo = __floats2half2_rn(v.x, v.y);
            __half2 hi = __floats2half2_rn(v.z, v.w);
            *(uint2*)&Xs[r * XS_STRIDE + c4 * 4] =
                make_uint2(*(unsigned*)&lo, *(unsigned*)&hi);
        }
    } else {
        for (int i = tid; i < 128 * 16; i += 256) {
            int r = i >> 4, c8 = i & 15;
            int gr = row0 + r;
            uint4 v = make_uint4(0u, 0u, 0u, 0u);
            if (gr < N) v = __ldg((const uint4*)(g_h1 + (size_t)gr * D) + c8);
            *(uint4*)&Xs[r * XS_STRIDE + c8 * 8] = v;
        }
    }
    __syncthreads();

    float acc[16][4];
    #pragma unroll
    for (int nt = 0; nt < 16; nt++)
        acc[nt][0] = acc[nt][1] = acc[nt][2] = acc[nt][3] = 0.f;

    int a_row = (lane & 7) | (((lane >> 3) & 1) << 3);
    int a_col8 = (lane >> 4) * 8;
    const __half* a_base = &Xs[(wid * 16 + a_row) * XS_STRIDE + a_col8];
    const uint2* Wb = g_wb[layer];

    #pragma unroll
    for (int ks = 0; ks < 8; ks++) {
        uint32_t a0, a1, a2, a3;
        uint32_t addr = (uint32_t)__cvta_generic_to_shared(a_base + ks * 16);
        asm volatile(
            "ldmatrix.sync.aligned.m8n8.x4.shared.b16 {%0,%1,%2,%3}, [%4];"
            : "=r"(a0), "=r"(a1), "=r"(a2), "=r"(a3) : "r"(addr));
        #pragma unroll
        for (int nt = 0; nt < 16; nt++) {
            uint2 b = __ldg(Wb + (ks * 16 + nt) * 32 + lane);
            asm volatile(
                "mma.sync.aligned.m16n8k16.row.col.f32.f16.f16.f32 "
                "{%0,%1,%2,%3},{%4,%5,%6,%7},{%8,%9},{%0,%1,%2,%3};"
                : "+f"(acc[nt][0]), "+f"(acc[nt][1]),
                  "+f"(acc[nt][2]), "+f"(acc[nt][3])
                : "r"(a0), "r"(a1), "r"(a2), "r"(a3), "r"(b.x), "r"(b.y));
        }
    }

    int tig = lane & 3, gid = lane >> 2;
    int r_lo = row0 + wid * 16 + gid;
    int r_hi = r_lo + 8;
    #pragma unroll
    for (int nt = 0; nt < 16; nt++) {
        int col = nt * 8 + tig * 2;
        if (r_lo < N) {
            __half2 h = __floats2half2_rn(acc[nt][0], acc[nt][1]);
            *(unsigned*)&g_h2[(size_t)r_lo * D + col] = *(unsigned*)&h;
        }
        if (r_hi < N) {
            __half2 h = __floats2half2_rn(acc[nt][2], acc[nt][3]);
            *(unsigned*)&g_h2[(size_t)r_hi * D + col] = *(unsigned*)&h;
        }
    }
}

// ---------------------------------------------------------------------------
// Aggregation (proven loop body): warp per node, lane covers 4 cols, __ldg.
__device__ __forceinline__ void agg_edge(float4& acc, const __half* T,
                                         int s, float c, int lane) {
    uint2 p = __ldg((const uint2*)(T + (size_t)s * D) + lane);
    float2 v0 = __half22float2(*(const __half2*)&p.x);
    float2 v1 = __half22float2(*(const __half2*)&p.y);
    acc.x = fmaf(c, v0.x, acc.x);
    acc.y = fmaf(c, v0.y, acc.y);
    acc.z = fmaf(c, v1.x, acc.z);
    acc.w = fmaf(c, v1.y, acc.w);
}

__device__ __forceinline__ float4 agg_node(const float* __restrict__ bias,
                                           int n, int lane, int j, int end) {
    const __half* T = g_h2;
    float di = g_dinv[n];
    float cs = di * di;
    float4 acc = make_float4(0.f, 0.f, 0.f, 0.f);
    agg_edge(acc, T, n, cs, lane);   // self-loop

    for (; j + 4 <= end; j += 4) {
        int2 e0 = g_csr[j + 0];
        int2 e1 = g_csr[j + 1];
        int2 e2 = g_csr[j + 2];
        int2 e3 = g_csr[j + 3];
        agg_edge(acc, T, e0.x, __int_as_float(e0.y), lane);
        agg_edge(acc, T, e1.x, __int_as_float(e1.y), lane);
        agg_edge(acc, T, e2.x, __int_as_float(e2.y), lane);
        agg_edge(acc, T, e3.x, __int_as_float(e3.y), lane);
    }
    for (; j < end; j++) {
        int2 e = g_csr[j];
        agg_edge(acc, T, e.x, __int_as_float(e.y), lane);
    }

    float4 b = __ldg((const float4*)bias + lane);
    acc.x = fmaxf(acc.x + b.x, 0.f);
    acc.y = fmaxf(acc.y + b.y, 0.f);
    acc.z = fmaxf(acc.z + b.z, 0.f);
    acc.w = fmaxf(acc.w + b.w, 0.f);
    return acc;
}

// layers 1-2: write h1 (fp16)
__global__ void __launch_bounds__(256)
k_agg(const float* __restrict__ bias, int N, int nb) {
    __shared__ int s_pref[16];
    load_bpref(s_pref, nb);
    __syncthreads();
    int warp = (blockIdx.x * blockDim.x + threadIdx.x) >> 5;
    int lane = threadIdx.x & 31;
    if (warp >= N) return;
    int j   = g_off[warp]     + s_pref[warp >> 12];
    int end = g_off[warp + 1] + s_pref[(warp + 1) >> 12];
    float4 acc = agg_node(bias, warp, lane, j, end);
    __half2 lo = __floats2half2_rn(acc.x, acc.y);
    __half2 hi = __floats2half2_rn(acc.z, acc.w);
    *(uint2*)(g_h1 + (size_t)warp * D + lane * 4) =
        make_uint2(*(unsigned*)&lo, *(unsigned*)&hi);
}

// layer 3 + pool: sorted-batch leader reduction, then per-segment atomics
__global__ void __launch_bounds__(256)
k_agg_pool(const float* __restrict__ bias, const int* __restrict__ batch,
           float* __restrict__ out, int N, int nb) {
    __shared__ int s_pref[16];
    __shared__ int s_g[8];
    __shared__ float s_acc[8 * 128];
    load_bpref(s_pref, nb);
    __syncthreads();
    int tid = threadIdx.x;
    int wid = tid >> 5, lane = tid & 31;
    int warp = (blockIdx.x * blockDim.x + tid) >> 5;
    bool valid = warp < N;

    float4 acc = make_float4(0.f, 0.f, 0.f, 0.f);
    int g = -1;
    if (valid) {
        int j   = g_off[warp]     + s_pref[warp >> 12];
        int end = g_off[warp + 1] + s_pref[(warp + 1) >> 12];
        acc = agg_node(bias, warp, lane, j, end);
        g = batch[warp];
    }
    if (lane == 0) s_g[wid] = g;
    *(float4*)&s_acc[wid * 128 + lane * 4] = acc;
    __syncthreads();

    int myg = s_g[wid];
    bool leader = (myg >= 0) && (wid == 0 || s_g[wid - 1] != myg);
    if (leader) {
        float4 sum = *(float4*)&s_acc[wid * 128 + lane * 4];
        for (int w = wid + 1; w < 8 && s_g[w] == myg; w++) {
            float4 t = *(float4*)&s_acc[w * 128 + lane * 4];
            sum.x += t.x; sum.y += t.y; sum.z += t.z; sum.w += t.w;
        }
        float* o = out + (size_t)myg * D + lane * 4;
        atomicAdd(o + 0, sum.x);
        atomicAdd(o + 1, sum.y);
        atomicAdd(o + 2, sum.z);
        atomicAdd(o + 3, sum.w);
    }
}

__global__ void k_div(float* __restrict__ out) {
    int i = blockIdx.x * blockDim.x + threadIdx.x;
    if (i < NGRAPH * D) out[i] = out[i] / fmaxf(g_gcnt[i >> 7], 1.f);
}

// ---------------------------------------------------------------------------
extern "C" void kernel_launch(void* const* d_in, const int* in_sizes, int n_in,
                              void* d_out, int out_size) {
    const float* x  = (const float*)d_in[0];
    // d_in[1] = edge_attr (unused)
    const float* W1 = (const float*)d_in[2];
    const float* b1 = (const float*)d_in[3];
    const float* W2 = (const float*)d_in[4];
    const float* b2 = (const float*)d_in[5];
    const float* W3 = (const float*)d_in[6];
    const float* b3 = (const float*)d_in[7];
    const int* ei    = (const int*)d_in[8];
    const int* batch = (const int*)d_in[9];
    float* out = (float*)d_out;

    int N = in_sizes[0] / D;
    int E = in_sizes[8] / 2;
    const int* src = ei;
    const int* dst = ei + E;

    int span = N > NGRAPH * D ? N : NGRAPH * D;
    int initb = (span + 255) / 256;
    int eb = (E + 255) / 256;
    int gb = (N + 127) / 128;
    int ab = ((N * 32) + 255) / 256;
    int sb = (N + SCAN_ELEMS - 1) / SCAN_ELEMS;

    // side stream: {wconv, gemm1} overlap the CSR build on the main stream.
    cudaStream_t s2;
    cudaStreamCreateWithFlags(&s2, cudaStreamNonBlocking);
    cudaEvent_t evF, evJ;
    cudaEventCreateWithFlags(&evF, cudaEventDisableTiming);
    cudaEventCreateWithFlags(&evJ, cudaEventDisableTiming);

    cudaEventRecord(evF, 0);
    cudaStreamWaitEvent(s2, evF, 0);
    k_wconv<<<48, 256, 0, s2>>>(W1, W2, W3);
    k_gemm<<<gb, 256, 0, s2>>>(x, 0, N, 1);        // layer-1 GEMM -> g_h2
    cudaEventRecord(evJ, s2);

    // main stream: CSR build (replicated count)
    k_zero<<<initb, 256>>>(out, N);
    bool vec4 = (E % 4 == 0) && ((((uintptr_t)dst) & 15) == 0);
    if (vec4) {
        int E4 = E / 4;
        int nt = (E4 + 1) / 2;
        k_count8<<<(nt + 255) / 256, 256>>>((const int4*)dst, E4);
    } else {
        k_count1<<<eb, 256>>>(dst, E);
    }
    k_scan1<<<sb, SCAN_T>>>(batch, N);
    k_fill<<<eb, 256>>>(src, dst, E, sb);

    // join: agg needs both g_h2 (s2) and CSR (main)
    cudaStreamWaitEvent(0, evJ, 0);

    // layer 1 agg: h2 -> h1
    k_agg<<<ab, 256>>>(b1, N, sb);
    // layer 2: h1 -> h2 -> h1
    k_gemm<<<gb, 256>>>(x, 1, N, 0);
    k_agg<<<ab, 256>>>(b2, N, sb);
    // layer 3: h1 -> h2 -> out (leader-reduced pool)
    k_gemm<<<gb, 256>>>(x, 2, N, 0);
    k_agg_pool<<<ab, 256>>>(b3, batch, out, N, sb);

    k_div<<<(NGRAPH * D + 255) / 256, 256>>>(out);
}